// round 8
// baseline (speedup 1.0000x reference)
#include <cuda_runtime.h>

// PhotonicMesh: 512-port Clements mesh, 512 layers, 1024 batch rows.
// R8: each row split across a WARP PAIR (lane owns 8 ports) like R5, but
// launched as 1024 CTAs x 64 threads (CTA = one row) so ~7 CTAs land on
// each of the 148+ SMs => ~3.5 warps/SMSP (2x R7's occupancy), while the
// per-2-layer barrier couples only the row's own 2 warps.
// Warp-half h owns ports [256h+8t, 256h+8t+8) at lane t. Even layers fully
// lane-local; odd layers: 3 local pairs + cross pair (s7, next s0) via
// shuffle, warp-pair boundary (ports 255/256) via parity-double-buffered
// 4-float smem slot + ONE __syncthreads per 2 layers.

#define N_PORT  512
#define N_LAYER 512
#define ATTEN_F 0.97723722095581054f   // sqrt(10^(-0.2/10))

// Coefficient table: entry [(l*4 + k)*64 + 32h + t] holds float4
// (ct*ATTEN, st*ATTEN, cos(phi), sin(phi)) for pair p = 128h + 4t + k of
// layer l (identity for invalid pairs). Warp reads 512B coalesced per k.
__device__ float4 g_tab[N_LAYER * 4 * 64];

__global__ void pm_coef_kernel(const float* __restrict__ thetas,
                               const float* __restrict__ phis,
                               const int*   __restrict__ mzi_idx) {
    int l   = blockIdx.x;
    int tid = threadIdx.x;            // 256
    int t = tid & 31;
    int h = (tid >> 5) & 1;
    int k = tid >> 6;                 // 0..3
    int p = 128 * h + 4 * t + k;
    bool odd = (l & 1) != 0;
    float4 c = make_float4(1.f, 0.f, 1.f, 0.f);   // identity
    bool valid = odd ? (p < 255) : true;          // odd layers: 255 pairs
    if (valid) {
        int u = odd ? (2 * p + 1) : (2 * p);      // upper port of pair
        int m = mzi_idx[l * N_PORT + u];
        float st, ct, sp, cp;
        sincosf(thetas[m], &st, &ct);
        sincosf(phis[m],   &sp, &cp);
        c = make_float4(ct * ATTEN_F, st * ATTEN_F, cp, sp);
    }
    g_tab[(l * 4 + k) * 64 + 32 * h + t] = c;
}

// new_i = e^{i phi}(ct*x_i + st*x_j) ; new_j = ct*x_j - st*x_i
__device__ __forceinline__ void butterfly(float2& xi, float2& xj, float4 c) {
    float ct = c.x, st = c.y, er = c.z, ei = c.w;
    float ur = ct * xi.x + st * xj.x;
    float ui = ct * xi.y + st * xj.y;
    float vr = ct * xj.x - st * xi.x;
    float vi = ct * xj.y - st * xi.y;
    xi.x = er * ur - ei * ui;
    xi.y = er * ui + ei * ur;
    xj.x = vr;
    xj.y = vi;
}

__global__ __launch_bounds__(64)
void pm_mesh_kernel(const float* __restrict__ x, float* __restrict__ out) {
    // boundary exchange: [parity][h0s7.re, h0s7.im, h1s0.re, h1s0.im]
    __shared__ float buf[2][4];

    const int lane = threadIdx.x & 31;
    const int h    = threadIdx.x >> 5;     // warp-half: 0 = ports 0..255
    const int row  = blockIdx.x;           // one row per CTA
    const int base = 32 * h + lane;        // coefficient lane index

    float2 s[8];   // lane owns ports 256h+8*lane .. +8

    // ---- load input (real), imag = 0 ----
    {
        const float4* x4 = reinterpret_cast<const float4*>(x);
        size_t off = (size_t)row * (N_PORT / 4) + h * 64 + lane * 2;
        float4 a0 = x4[off];
        float4 a1 = x4[off + 1];
        s[0] = make_float2(a0.x, 0.f); s[1] = make_float2(a0.y, 0.f);
        s[2] = make_float2(a0.z, 0.f); s[3] = make_float2(a0.w, 0.f);
        s[4] = make_float2(a1.x, 0.f); s[5] = make_float2(a1.y, 0.f);
        s[6] = make_float2(a1.z, 0.f); s[7] = make_float2(a1.w, 0.f);
    }

    float4 A[4], B[4], cx = make_float4(1.f, 0.f, 1.f, 0.f);
    #pragma unroll
    for (int k = 0; k < 4; k++) A[k] = __ldg(&g_tab[k * 64 + base]);

    #pragma unroll 1
    for (int l = 0; l < N_LAYER; l += 2) {
        // prefetch odd layer l+1
        #pragma unroll
        for (int k = 0; k < 4; k++)
            B[k] = __ldg(&g_tab[((l + 1) * 4 + k) * 64 + base]);
        // h1 lane0 also needs pair 127's coef (slot k=3, h=0, t=31)
        if (h == 1 && lane == 0)
            cx = __ldg(&g_tab[((l + 1) * 4 + 3) * 64 + 31]);

        // ---- EVEN layer l: pairs (s0,s1)(s2,s3)(s4,s5)(s6,s7), lane-local ----
        #pragma unroll
        for (int k = 0; k < 4; k++)
            butterfly(s[2 * k], s[2 * k + 1], A[k]);

        // publish warp-pair boundary values (post-even snapshots)
        const int par = (l >> 1) & 1;
        if (h == 0 && lane == 31) { buf[par][0] = s[7].x; buf[par][1] = s[7].y; }
        if (h == 1 && lane == 0)  { buf[par][2] = s[0].x; buf[par][3] = s[0].y; }

        // prefetch even layer l+2 (in flight across the barrier)
        int ln = (l + 2 < N_LAYER) ? (l + 2) : 0;
        #pragma unroll
        for (int k = 0; k < 4; k++)
            A[k] = __ldg(&g_tab[(ln * 4 + k) * 64 + base]);

        __syncthreads();

        // ---- ODD layer l+1 ----
        // pre-update snapshots
        float nx0r = __shfl_down_sync(0xffffffffu, s[0].x, 1);  // next lane s0
        float nx0i = __shfl_down_sync(0xffffffffu, s[0].y, 1);
        float px7r = __shfl_up_sync  (0xffffffffu, s[7].x, 1);  // prev lane s7
        float px7i = __shfl_up_sync  (0xffffffffu, s[7].y, 1);
        float ctp  = __shfl_up_sync  (0xffffffffu, B[3].x, 1);  // prev cross coef
        float stp  = __shfl_up_sync  (0xffffffffu, B[3].y, 1);
        if (h == 0 && lane == 31) {                 // partner = port 256 (warp 1)
            nx0r = buf[par][2]; nx0i = buf[par][3];
        }
        if (h == 1 && lane == 0) {                  // partner = port 255 (warp 0)
            px7r = buf[par][0]; px7i = buf[par][1];
            ctp = cx.x; stp = cx.y;
        }
        if (h == 0 && lane == 0) { ctp = 1.f; stp = 0.f; }  // global port 0 pass

        // local pairs (s1,s2)(s3,s4)(s5,s6)
        butterfly(s[1], s[2], B[0]);
        butterfly(s[3], s[4], B[1]);
        butterfly(s[5], s[6], B[2]);

        // cross pair upper port (s7) with partner nx0; identity coef at port 511
        {
            float ct = B[3].x, st = B[3].y, er = B[3].z, ei = B[3].w;
            float ur = ct * s[7].x + st * nx0r;
            float ui = ct * s[7].y + st * nx0i;
            s[7].x = er * ur - ei * ui;
            s[7].y = er * ui + ei * ur;
        }
        // cross pair lower port (s0) with partner px7 (real coefficients)
        {
            float2 x0 = s[0];
            s[0].x = ctp * x0.x - stp * px7r;
            s[0].y = ctp * x0.y - stp * px7i;
        }
    }

    // ---- square-law detection + store ----
    {
        float4 o0, o1;
        o0.x = s[0].x * s[0].x + s[0].y * s[0].y;
        o0.y = s[1].x * s[1].x + s[1].y * s[1].y;
        o0.z = s[2].x * s[2].x + s[2].y * s[2].y;
        o0.w = s[3].x * s[3].x + s[3].y * s[3].y;
        o1.x = s[4].x * s[4].x + s[4].y * s[4].y;
        o1.y = s[5].x * s[5].x + s[5].y * s[5].y;
        o1.z = s[6].x * s[6].x + s[6].y * s[6].y;
        o1.w = s[7].x * s[7].x + s[7].y * s[7].y;
        float4* o4 = reinterpret_cast<float4*>(out);
        size_t off = (size_t)row * (N_PORT / 4) + h * 64 + lane * 2;
        o4[off]     = o0;
        o4[off + 1] = o1;
    }
}

extern "C" void kernel_launch(void* const* d_in, const int* in_sizes, int n_in,
                              void* d_out, int out_size) {
    const float* x       = (const float*)d_in[0];
    const float* thetas  = (const float*)d_in[1];
    const float* phis    = (const float*)d_in[2];
    // d_in[3] = partner (unused: structure is static)
    const int*   mzi_idx = (const int*)d_in[4];
    // d_in[5] = role (unused: structure is static)
    float* out = (float*)d_out;

    pm_coef_kernel<<<N_LAYER, 256>>>(thetas, phis, mzi_idx);
    // 1024 CTAs x 2 warps: CTA = one row; ~7 CTAs/SM on 148+ SMs
    pm_mesh_kernel<<<1024, 64>>>(x, out);
}

// round 9
// speedup vs baseline: 1.2141x; 1.2141x over previous
#include <cuda_runtime.h>

// PhotonicMesh: 512-port Clements mesh, 512 layers, 1024 batch rows.
// R9 = R7 (best, 118.8us: 1024 single-warp CTAs, lane owns 16 ports,
// ping-pong coef prefetch) with two latency fixes in the layer loop:
//  (a) BRANCHLESS odd layer: lane31's cross pair uses the table's identity
//      coefficient (pair 255) so `if (lane<31)` is removed; lane0's cross
//      coefficient is forced to identity via 2 SELs at load time so
//      `if (lane>0)` is removed. No BSSY/BSYNC in the hot loop.
//  (b) Even-layer reorder: boundary pairs (k=0, k=7) computed FIRST and the
//      4 odd-layer shuffles issued immediately after, so their ~26-cycle
//      latency hides under the remaining 6 even + 7 odd local butterflies.

#define N_PORT  512
#define N_LAYER 512
#define N_PAIR  256
#define ATTEN_F 0.97723722095581054f   // sqrt(10^(-0.2/10))

// Coefficient table, layout: [(l*8 + k)*32 + lane] where pair p = 8*lane + k.
// Per-k load across a warp is a fully coalesced 512B read.
__device__ float4 g_coef[N_LAYER * N_PAIR];

__global__ void pm_coef_kernel(const float* __restrict__ thetas,
                               const float* __restrict__ phis,
                               const int*   __restrict__ mzi_idx) {
    int l = blockIdx.x;      // layer
    int p = threadIdx.x;     // pair index within layer
    float4 c = make_float4(1.0f, 0.0f, 1.0f, 0.0f);  // identity (unused slots)
    bool odd = (l & 1) != 0;
    bool valid = (!odd) || (p < N_PAIR - 1);         // odd layers have 255 pairs
    if (valid) {
        int i = odd ? (2 * p + 1) : (2 * p);         // upper port of the pair
        int m = mzi_idx[l * N_PORT + i];
        float st, ct, sp, cp;
        sincosf(thetas[m], &st, &ct);
        sincosf(phis[m],   &sp, &cp);
        c = make_float4(ct * ATTEN_F, st * ATTEN_F, cp, sp);
    }
    g_coef[(l * 8 + (p & 7)) * 32 + (p >> 3)] = c;
}

// new_i = e^{i phi}(ct*x_i + st*x_j) ; new_j = ct*x_j - st*x_i
__device__ __forceinline__ void butterfly(float2& xi, float2& xj, float4 c) {
    float ct = c.x, st = c.y, er = c.z, ei = c.w;
    float ur = ct * xi.x + st * xj.x;
    float ui = ct * xi.y + st * xj.y;
    float vr = ct * xj.x - st * xi.x;
    float vi = ct * xj.y - st * xi.y;
    xi.x = er * ur - ei * ui;
    xi.y = er * ui + ei * ur;
    xj.x = vr;
    xj.y = vi;
}

// Load coefficients for even layer l (c[0..7]) and odd layer l+1 (c[8..15]).
// c[16].x/.y = cross-pair (ct, st) owned by lane-1 (pair 8*(lane-1)+7 of
// layer l+1), forced to identity at lane 0 (global port 0 passthrough).
__device__ __forceinline__ void load_coefs(float4* c, int l, int lane) {
    const float4* ce = g_coef + (size_t)l * N_PAIR;
    const float4* co = g_coef + (size_t)(l + 1) * N_PAIR;
    #pragma unroll
    for (int k = 0; k < 8; k++) c[k]     = __ldg(&ce[k * 32 + lane]);
    #pragma unroll
    for (int k = 0; k < 8; k++) c[k + 8] = __ldg(&co[k * 32 + lane]);
    int lm = (lane > 0) ? (lane - 1) : 0;
    float4 cx = __ldg(&co[7 * 32 + lm]);
    c[16].x = (lane > 0) ? cx.x : 1.0f;   // SEL, not branch
    c[16].y = (lane > 0) ? cx.y : 0.0f;
    c[16].z = 1.0f; c[16].w = 0.0f;
}

// Two layers (even l, odd l+1), fully branch-free.
// c[0..7] even pairs, c[8..15] odd pairs, c[16] lane-1 cross coef.
__device__ __forceinline__ void step2(float2* s, const float4* c) {
    // -- even boundary pairs first, so shuffles can issue early --
    butterfly(s[0],  s[1],  c[0]);
    butterfly(s[14], s[15], c[7]);
    // odd-layer neighbor snapshots (post-even values of s0/s15)
    float xjr = __shfl_down_sync(0xffffffffu, s[0].x, 1);   // (lane+1).port0
    float xji = __shfl_down_sync(0xffffffffu, s[0].y, 1);
    float xir = __shfl_up_sync(0xffffffffu, s[15].x, 1);    // (lane-1).port15
    float xii = __shfl_up_sync(0xffffffffu, s[15].y, 1);
    // -- remaining even pairs (overlap the shuffle latency) --
    #pragma unroll
    for (int k = 1; k < 7; k++)
        butterfly(s[2 * k], s[2 * k + 1], c[k]);
    // -- odd local pairs (2k+1, 2k+2), independent of shuffles --
    #pragma unroll
    for (int k = 0; k < 7; k++)
        butterfly(s[2 * k + 1], s[2 * k + 2], c[8 + k]);
    // -- cross pair upper port s15: lane31 coef is identity (table pair 255),
    //    so no guard; shfl garbage is multiplied by st=0 --
    {
        float ct = c[15].x, st = c[15].y, er = c[15].z, ei = c[15].w;
        float ur = ct * s[15].x + st * xjr;
        float ui = ct * s[15].y + st * xji;
        s[15].x = er * ur - ei * ui;
        s[15].y = er * ui + ei * ur;
    }
    // -- cross pair lower port s0: lane0 coef forced to identity at load --
    {
        float2 x0 = s[0];
        s[0].x = c[16].x * x0.x - c[16].y * xir;
        s[0].y = c[16].x * x0.y - c[16].y * xii;
    }
}

__global__ __launch_bounds__(32)
void pm_mesh_kernel(const float* __restrict__ x, float* __restrict__ out) {
    const int lane = threadIdx.x & 31;
    const int row  = blockIdx.x;          // one warp-CTA per batch row

    float2 s[16];             // complex state: lane owns ports 16*lane..16*lane+15

    // ---- load input (real), imag = 0 ----
    const float4* x4 = reinterpret_cast<const float4*>(x);
    #pragma unroll
    for (int v = 0; v < 4; v++) {
        float4 q = x4[(size_t)row * (N_PORT / 4) + lane * 4 + v];
        s[4 * v + 0] = make_float2(q.x, 0.f);
        s[4 * v + 1] = make_float2(q.y, 0.f);
        s[4 * v + 2] = make_float2(q.z, 0.f);
        s[4 * v + 3] = make_float2(q.w, 0.f);
    }

    // ---- software-pipelined propagation: ping-pong coefficient buffers ----
    float4 cA[17], cB[17];
    load_coefs(cA, 0, lane);

    // Each outer iteration processes 4 layers (A then B) while prefetching.
    #pragma unroll 1
    for (int l = 0; l < N_LAYER; l += 4) {
        int ln1 = l + 2;  if (ln1 > N_LAYER - 2) ln1 = 0;   // clamp (result unused)
        load_coefs(cB, ln1, lane);
        step2(s, cA);

        int ln2 = l + 4;  if (ln2 > N_LAYER - 2) ln2 = 0;   // clamp (result unused)
        load_coefs(cA, ln2, lane);
        step2(s, cB);
    }

    // ---- square-law detection + store ----
    float4* o4 = reinterpret_cast<float4*>(out);
    #pragma unroll
    for (int v = 0; v < 4; v++) {
        float4 q;
        q.x = s[4 * v + 0].x * s[4 * v + 0].x + s[4 * v + 0].y * s[4 * v + 0].y;
        q.y = s[4 * v + 1].x * s[4 * v + 1].x + s[4 * v + 1].y * s[4 * v + 1].y;
        q.z = s[4 * v + 2].x * s[4 * v + 2].x + s[4 * v + 2].y * s[4 * v + 2].y;
        q.w = s[4 * v + 3].x * s[4 * v + 3].x + s[4 * v + 3].y * s[4 * v + 3].y;
        o4[(size_t)row * (N_PORT / 4) + lane * 4 + v] = q;
    }
}

extern "C" void kernel_launch(void* const* d_in, const int* in_sizes, int n_in,
                              void* d_out, int out_size) {
    const float* x       = (const float*)d_in[0];
    const float* thetas  = (const float*)d_in[1];
    const float* phis    = (const float*)d_in[2];
    // d_in[3] = partner (unused: structure is static)
    const int*   mzi_idx = (const int*)d_in[4];
    // d_in[5] = role (unused: structure is static)
    float* out = (float*)d_out;

    pm_coef_kernel<<<N_LAYER, N_PAIR>>>(thetas, phis, mzi_idx);
    // 1024 single-warp CTAs: spread across ALL SMs (~7 per SM on 148+ SMs)
    pm_mesh_kernel<<<1024, 32>>>(x, out);
}

// round 10
// speedup vs baseline: 1.4245x; 1.1733x over previous
#include <cuda_runtime.h>

// PhotonicMesh: 512-port Clements mesh, 512 layers, 1024 batch rows.
// R10 = R7 skeleton (best, 118.8us: 1024 single-warp CTAs, lane owns 16
// ports, guarded odd layer) with the coefficient double-buffer moved from
// REGISTERS to SHARED MEMORY via cp.async:
//   R7/R9 spilled (live set ~170 regs vs 132 allocated -> local STL/LDL =
//   the mystery L1 traffic). Now each lane cp.asyncs its 17 float4 per
//   2-layer step into a 2-buffer smem ring (own slots only, incl. a private
//   copy of the lane-1 cross coefficient => no cross-lane smem reads, no
//   barriers; per-thread cp.async.wait_group is enough for a 1-warp CTA).
//   Compute LDSes coefs in two short batches (8 even, 9 odd) so peak live
//   coef regs = 8 float4. No spills, fewer issue slots per iteration.

#define N_PORT  512
#define N_LAYER 512
#define N_PAIR  256
#define ATTEN_F 0.97723722095581054f   // sqrt(10^(-0.2/10))

// Coefficient table, layout: [(l*8 + k)*32 + lane] = [l*256 + k*32 + lane],
// pair p = 8*lane + k. A 2-layer block (l even) is 512 contiguous float4.
__device__ float4 g_coef[N_LAYER * N_PAIR];

__global__ void pm_coef_kernel(const float* __restrict__ thetas,
                               const float* __restrict__ phis,
                               const int*   __restrict__ mzi_idx) {
    int l = blockIdx.x;      // layer
    int p = threadIdx.x;     // pair index within layer
    float4 c = make_float4(1.0f, 0.0f, 1.0f, 0.0f);  // identity (unused slots)
    bool odd = (l & 1) != 0;
    bool valid = (!odd) || (p < N_PAIR - 1);         // odd layers have 255 pairs
    if (valid) {
        int i = odd ? (2 * p + 1) : (2 * p);         // upper port of the pair
        int m = mzi_idx[l * N_PORT + i];
        float st, ct, sp, cp;
        sincosf(thetas[m], &st, &ct);
        sincosf(phis[m],   &sp, &cp);
        c = make_float4(ct * ATTEN_F, st * ATTEN_F, cp, sp);
    }
    g_coef[(l * 8 + (p & 7)) * 32 + (p >> 3)] = c;
}

// new_i = e^{i phi}(ct*x_i + st*x_j) ; new_j = ct*x_j - st*x_i
__device__ __forceinline__ void butterfly(float2& xi, float2& xj, float4 c) {
    float ct = c.x, st = c.y, er = c.z, ei = c.w;
    float ur = ct * xi.x + st * xj.x;
    float ui = ct * xi.y + st * xj.y;
    float vr = ct * xj.x - st * xi.x;
    float vi = ct * xj.y - st * xi.y;
    xi.x = er * ur - ei * ui;
    xi.y = er * ui + ei * ur;
    xj.x = vr;
    xj.y = vi;
}

__device__ __forceinline__ void cp_async16(unsigned dst_smem, const void* src) {
    asm volatile("cp.async.cg.shared.global [%0], [%1], 16;"
                 :: "r"(dst_smem), "l"(src));
}

__global__ __launch_bounds__(32)
void pm_mesh_kernel(const float* __restrict__ x, float* __restrict__ out) {
    // 2-buffer coefficient ring: [buf][slot k=0..16][lane]
    __shared__ float4 sc[2][17 * 32];

    const int lane = threadIdx.x & 31;
    const int row  = blockIdx.x;          // one warp-CTA per batch row

    float2 s[16];             // complex state: lane owns ports 16*lane..16*lane+15

    // ---- load input (real), imag = 0 ----
    const float4* x4 = reinterpret_cast<const float4*>(x);
    #pragma unroll
    for (int v = 0; v < 4; v++) {
        float4 q = x4[(size_t)row * (N_PORT / 4) + lane * 4 + v];
        s[4 * v + 0] = make_float2(q.x, 0.f);
        s[4 * v + 1] = make_float2(q.y, 0.f);
        s[4 * v + 2] = make_float2(q.z, 0.f);
        s[4 * v + 3] = make_float2(q.w, 0.f);
    }

    const int lm = (lane > 0) ? (lane - 1) : 0;   // lane0 value unused (guard)

    // stage coefficients for 2-layer block starting at even layer l into buf
    auto stage = [&](int buf, int l) {
        unsigned d0 = (unsigned)__cvta_generic_to_shared(&sc[buf][lane]);
        const float4* g = g_coef + (size_t)l * 256 + lane;
        #pragma unroll
        for (int k = 0; k < 16; k++)
            cp_async16(d0 + (unsigned)(k * 32 * 16), g + k * 32);
        // private copy of lane-1's cross coef (odd layer, pair slot k=7)
        cp_async16((unsigned)__cvta_generic_to_shared(&sc[buf][16 * 32 + lane]),
                   g_coef + (size_t)(l + 1) * 256 + 7 * 32 + lm);
        asm volatile("cp.async.commit_group;" ::: "memory");
    };

    stage(0, 0);
    stage(1, 2);

    #pragma unroll 1
    for (int l = 0; l < N_LAYER; l += 2) {
        asm volatile("cp.async.wait_group 1;" ::: "memory");
        const int buf = (l >> 1) & 1;

        float4 c[8];

        // ---- EVEN layer l: pairs (16*lane+2k, +2k+1), lane-local ----
        #pragma unroll
        for (int k = 0; k < 8; k++) c[k] = sc[buf][k * 32 + lane];
        #pragma unroll
        for (int k = 0; k < 8; k++)
            butterfly(s[2 * k], s[2 * k + 1], c[k]);

        // ---- ODD layer l+1 ----
        #pragma unroll
        for (int k = 0; k < 8; k++) c[k] = sc[buf][(8 + k) * 32 + lane];
        float4 cx = sc[buf][16 * 32 + lane];

        // snapshot neighbor values BEFORE any update this layer
        float xjr = __shfl_down_sync(0xffffffffu, s[0].x, 1);   // (lane+1).port0
        float xji = __shfl_down_sync(0xffffffffu, s[0].y, 1);
        float xir = __shfl_up_sync(0xffffffffu, s[15].x, 1);    // (lane-1).port15
        float xii = __shfl_up_sync(0xffffffffu, s[15].y, 1);
        #pragma unroll
        for (int k = 0; k < 7; k++)
            butterfly(s[2 * k + 1], s[2 * k + 2], c[k]);
        if (lane < 31) {  // upper port of cross pair: gets the phase
            float ct = c[7].x, st = c[7].y, er = c[7].z, ei = c[7].w;
            float ur = ct * s[15].x + st * xjr;
            float ui = ct * s[15].y + st * xji;
            s[15].x = er * ur - ei * ui;
            s[15].y = er * ui + ei * ur;
        }
        if (lane > 0) {   // lower port of cross pair: real coefficients
            float2 x0 = s[0];
            s[0].x = cx.x * x0.x - cx.y * xir;
            s[0].y = cx.x * x0.y - cx.y * xii;
        }

        // refill this buffer for layers l+4 (clamped; tail data never used)
        int ln = l + 4;  if (ln > N_LAYER - 2) ln = 0;
        stage(buf, ln);
    }

    // ---- square-law detection + store ----
    float4* o4 = reinterpret_cast<float4*>(out);
    #pragma unroll
    for (int v = 0; v < 4; v++) {
        float4 q;
        q.x = s[4 * v + 0].x * s[4 * v + 0].x + s[4 * v + 0].y * s[4 * v + 0].y;
        q.y = s[4 * v + 1].x * s[4 * v + 1].x + s[4 * v + 1].y * s[4 * v + 1].y;
        q.z = s[4 * v + 2].x * s[4 * v + 2].x + s[4 * v + 2].y * s[4 * v + 2].y;
        q.w = s[4 * v + 3].x * s[4 * v + 3].x + s[4 * v + 3].y * s[4 * v + 3].y;
        o4[(size_t)row * (N_PORT / 4) + lane * 4 + v] = q;
    }
}

extern "C" void kernel_launch(void* const* d_in, const int* in_sizes, int n_in,
                              void* d_out, int out_size) {
    const float* x       = (const float*)d_in[0];
    const float* thetas  = (const float*)d_in[1];
    const float* phis    = (const float*)d_in[2];
    // d_in[3] = partner (unused: structure is static)
    const int*   mzi_idx = (const int*)d_in[4];
    // d_in[5] = role (unused: structure is static)
    float* out = (float*)d_out;

    pm_coef_kernel<<<N_LAYER, N_PAIR>>>(thetas, phis, mzi_idx);
    // 1024 single-warp CTAs: spread across ALL SMs (~7 per SM on 148+ SMs)
    pm_mesh_kernel<<<1024, 32>>>(x, out);
}